// round 14
// baseline (speedup 1.0000x reference)
#include <cuda_runtime.h>
#include <cuda_fp16.h>
#include <mma.h>
using namespace nvcuda;

#define N_NODES 100000
#define N_EDGES 1600000
#define HID 128
#define NCTA 592                         // 148 SM x 4 CTA, co-residency guaranteed
#define CSR_T 256
#define PART ((N_NODES + NCTA - 1) / NCTA)   // 169 nodes per CTA chunk

typedef unsigned long long u64;
typedef unsigned int u32;

// Scratch (no cudaMalloc allowed). Features stored fp16 (aggregation math fp32).
__device__ __align__(16) __half g_Ah[(size_t)N_NODES * HID];  // GEMM outputs / message source
__device__ __align__(16) __half g_Bh[(size_t)N_NODES * HID];  // aggregated features
__device__ __align__(16) float  g_XA[(size_t)N_NODES * 5];    // aggregated raw input (fp32)
__device__ __align__(16) float  g_dinv[N_NODES];
__device__ int   g_cnt[N_NODES];
__device__ int   g_off[N_NODES];     // scan result; fill bumps it to segment END
__device__ int   g_part[NCTA];       // per-CTA chunk sums
__device__ u32   g_barc[8];          // global barrier counters (memset per call)
__device__ __align__(8) uint2 g_edge[N_EDGES];   // (src, dinv[src] bits) interleaved

// ---------------- global barrier (co-resident grid only) ----------------
__device__ __forceinline__ void gbar(int b) {
    __syncthreads();
    if (threadIdx.x == 0) {
        __threadfence();
        atomicAdd(g_barc + b, 1u);
        while (*(volatile u32*)(g_barc + b) < (u32)NCTA) __nanosleep(64);
    }
    __syncthreads();
}

// ---------------- persistent CSR build + layer-1 input aggregation ----------------
// P0 zero counts | P1 degree count | P2 dinv + chunk sums | P3 prefix + local scan
// P4 fill edges  | P5 agg_x (XA = Â X)
__global__ __launch_bounds__(CSR_T, 4) void k_csr(const int* __restrict__ src,
                                                  const int* __restrict__ dst,
                                                  const float* __restrict__ x) {
    __shared__ int sh[CSR_T];
    int tid = threadIdx.x;
    int gid = blockIdx.x * CSR_T + tid;
    const int stride = NCTA * CSR_T;                 // 151552

    // P0: zero g_cnt (one pass: stride >= N_NODES)
    if (gid < N_NODES) g_cnt[gid] = 0;
    gbar(0);

    // P1: degree count (2 edges per thread per iter)
    for (int p = gid; p < N_EDGES / 2; p += stride) {
        int2 dv = *(const int2*)(dst + p * 2);
        atomicAdd(&g_cnt[dv.x], 1);
        atomicAdd(&g_cnt[dv.y], 1);
    }
    gbar(1);

    // P2: dinv + per-CTA chunk sum
    {
        int cs = blockIdx.x * PART;
        int c = 0;
        if (tid < PART && cs + tid < N_NODES) {
            c = g_cnt[cs + tid];
            g_dinv[cs + tid] = rsqrtf((float)(c + 1));   // +1 self loop
        }
        sh[tid] = c;
        __syncthreads();
        #pragma unroll
        for (int off = CSR_T / 2; off > 0; off >>= 1) {
            if (tid < off) sh[tid] += sh[tid + off];
            __syncthreads();
        }
        if (tid == 0) g_part[blockIdx.x] = sh[0];
    }
    gbar(2);

    // P3: base = prefix of chunk sums, then local exclusive scan -> g_off
    {
        int s = 0;
        for (int j = tid; j < (int)blockIdx.x; j += CSR_T) s += g_part[j];
        sh[tid] = s;
        __syncthreads();
        #pragma unroll
        for (int off = CSR_T / 2; off > 0; off >>= 1) {
            if (tid < off) sh[tid] += sh[tid + off];
            __syncthreads();
        }
        int base = sh[0];
        __syncthreads();

        int cs = blockIdx.x * PART;
        int v = (tid < PART && cs + tid < N_NODES) ? g_cnt[cs + tid] : 0;
        sh[tid] = v;
        __syncthreads();
        #pragma unroll
        for (int off = 1; off < CSR_T; off <<= 1) {
            int cur = sh[tid];
            int a = (tid >= off) ? sh[tid - off] : 0;
            __syncthreads();
            sh[tid] = cur + a;
            __syncthreads();
        }
        if (tid < PART && cs + tid < N_NODES)
            g_off[cs + tid] = base + sh[tid] - v;        // exclusive
    }
    gbar(3);

    // P4: destructive fill (g_off -> segment END); interleaved 8B records
    for (int p = gid; p < N_EDGES / 2; p += stride) {
        int2 sv = *(const int2*)(src + p * 2);
        int2 dv = *(const int2*)(dst + p * 2);
        {
            int pos = atomicAdd(&g_off[dv.x], 1);
            uint2 ev; ev.x = (u32)sv.x; ev.y = __float_as_uint(g_dinv[sv.x]);
            g_edge[pos] = ev;
        }
        {
            int pos = atomicAdd(&g_off[dv.y], 1);
            uint2 ev; ev.x = (u32)sv.y; ev.y = __float_as_uint(g_dinv[sv.y]);
            g_edge[pos] = ev;
        }
    }
    gbar(4);

    // P5: agg_x — XA = Â X (5-wide, fp32); thread per node
    if (gid < N_NODES) {
        int i = gid;
        float dv = g_dinv[i];
        float acc[5];
        #pragma unroll
        for (int k = 0; k < 5; k++) acc[k] = dv * x[(size_t)i * 5 + k];
        int cnt = g_cnt[i];
        int start = g_off[i] - cnt;
        for (int j = 0; j < cnt; j++) {
            uint2 ev = g_edge[start + j];
            int s = (int)ev.x;
            float w = __uint_as_float(ev.y);
            #pragma unroll
            for (int k = 0; k < 5; k++) acc[k] = fmaf(w, x[(size_t)s * 5 + k], acc[k]);
        }
        #pragma unroll
        for (int k = 0; k < 5; k++) g_XA[(size_t)i * 5 + k] = dv * acc[k];
    }
}

// ---------------- aggregation: Bh = Â·Ah + bias  (warp/node; fp16 in/out, fp32 math) ----------------
__global__ __launch_bounds__(256) void k_agg(const float* __restrict__ bias) {
    int g = blockIdx.x * blockDim.x + threadIdx.x;
    int node = g >> 5;
    int lane = g & 31;
    if (node >= N_NODES) return;

    const uint2* __restrict__ A2 = (const uint2*)g_Ah;   // 4 halves per uint2; 32 uint2 per row
    float dv = g_dinv[node];
    uint2 raw = A2[(size_t)node * 32 + lane];
    float2 s0 = __half22float2(*(const half2*)&raw.x);
    float2 s1 = __half22float2(*(const half2*)&raw.y);
    float4 acc;
    acc.x = dv * s0.x; acc.y = dv * s0.y; acc.z = dv * s1.x; acc.w = dv * s1.y;

    int cnt = g_cnt[node];
    int start = g_off[node] - cnt;
    for (int j0 = 0; j0 < cnt; j0 += 32) {
        int  rem = cnt - j0;
        bool ok  = lane < rem;
        uint2 ev = ok ? g_edge[start + j0 + lane] : make_uint2(0u, 0u);
        int m = min(32, rem);
        #pragma unroll 8
        for (int j = 0; j < m; j++) {
            int   sj = (int)__shfl_sync(0xffffffffu, ev.x, j);
            float wj = __uint_as_float(__shfl_sync(0xffffffffu, ev.y, j));
            uint2 r = A2[(size_t)sj * 32 + lane];
            float2 f0 = __half22float2(*(const half2*)&r.x);
            float2 f1 = __half22float2(*(const half2*)&r.y);
            acc.x = fmaf(wj, f0.x, acc.x);
            acc.y = fmaf(wj, f0.y, acc.y);
            acc.z = fmaf(wj, f1.x, acc.z);
            acc.w = fmaf(wj, f1.y, acc.w);
        }
    }
    float4 bb = ((const float4*)bias)[lane];
    float2 o0, o1;
    o0.x = fmaf(dv, acc.x, bb.x);
    o0.y = fmaf(dv, acc.y, bb.y);
    o1.x = fmaf(dv, acc.z, bb.z);
    o1.y = fmaf(dv, acc.w, bb.w);
    half2 p0 = __float22half2_rn(o0);
    half2 p1 = __float22half2_rn(o1);
    uint2 w;
    w.x = *(const u32*)&p0;
    w.y = *(const u32*)&p1;
    ((uint2*)g_Bh)[(size_t)node * 32 + lane] = w;
}

// ---------------- tensor-core GEMM layout constants (128-row CTA tiles) ----------------
#define TILE_ROWS 128
#define A_PITCH 136              // halves (272 B rows)
#define W_PITCH 136
#define SC_PITCH 132             // floats
#define WH_BYTES (HID * W_PITCH * 2)            // 34816 (one W plane)
#define AT_BYTES (TILE_ROWS * A_PITCH * 2)      // 34816
#define L2_SMEM (2 * WH_BYTES + AT_BYTES + (5 * HID + HID) * 4)  // 107008 B
#define L3_SMEM (2 * WH_BYTES + AT_BYTES)                        // 104448 B

// split a float into hi/lo halves: w = hi + lo with |lo| <~ w*2^-12
__device__ __forceinline__ void split_h(float v, __half& hi, __half& lo) {
    hi = __float2half_rn(v);
    lo = __float2half_rn(v - __half2float(hi));
}

__device__ __forceinline__ void load_split_W(__half* Wh, __half* Wl,
                                             const float* __restrict__ W, int tid) {
    const float4* W4 = (const float4*)W;
    #pragma unroll
    for (int i = 0; i < 16; i++) {
        int idx4 = tid + 256 * i;                     // 0..4095
        int k = idx4 >> 5, c0 = (idx4 & 31) * 4;
        float4 v = W4[idx4];
        __half h0, l0, h1, l1, h2, l2, h3, l3;
        split_h(v.x, h0, l0); split_h(v.y, h1, l1);
        split_h(v.z, h2, l2); split_h(v.w, h3, l3);
        __half* wp = Wh + k * W_PITCH + c0;
        wp[0] = h0; wp[1] = h1; wp[2] = h2; wp[3] = h3;
        __half* lp = Wl + k * W_PITCH + c0;
        lp[0] = l0; lp[1] = l1; lp[2] = l2; lp[3] = l3;
    }
}

// shared mainloop + epilogue: warp 'warp' computes rows [warp*16, warp*16+16) x 128 cols
__device__ __forceinline__ void mma_tile_and_store(const __half* Wh, const __half* Wl,
                                                   const __half* At, float* sc,
                                                   __half* gout, int row0, int tid) {
    int warp = tid >> 5;
    wmma::fragment<wmma::accumulator, 16, 16, 16, float> fc[8];
    #pragma unroll
    for (int j = 0; j < 8; j++) wmma::fill_fragment(fc[j], 0.0f);
    #pragma unroll
    for (int k0 = 0; k0 < 8; k0++) {
        wmma::fragment<wmma::matrix_a, 16, 16, 16, __half, wmma::row_major> fa;
        wmma::load_matrix_sync(fa, At + warp * 16 * A_PITCH + k0 * 16, A_PITCH);
        #pragma unroll
        for (int j = 0; j < 8; j++) {
            wmma::fragment<wmma::matrix_b, 16, 16, 16, __half, wmma::row_major> fb;
            wmma::load_matrix_sync(fb, Wh + k0 * 16 * W_PITCH + j * 16, W_PITCH);
            wmma::mma_sync(fc[j], fa, fb, fc[j]);
            wmma::load_matrix_sync(fb, Wl + k0 * 16 * W_PITCH + j * 16, W_PITCH);
            wmma::mma_sync(fc[j], fa, fb, fc[j]);
        }
    }
    __syncthreads();                          // done reading W planes; reuse as fp32 scratch
    #pragma unroll
    for (int j = 0; j < 8; j++)
        wmma::store_matrix_sync(sc + warp * 16 * SC_PITCH + j * 16, fc[j],
                                SC_PITCH, wmma::mem_row_major);
    __syncthreads();
    // convert scratch -> gout (fp16): 128 rows x 32 col-quads, uint2 stores
    #pragma unroll
    for (int i = 0; i < 16; i++) {
        int li = tid + 256 * i;               // 0..4095
        int r = li >> 5, c4 = (li & 31) * 4;
        int grow = row0 + r;
        if (grow < N_NODES) {
            float4 v = *(float4*)&sc[r * SC_PITCH + c4];
            half2 p0 = __floats2half2_rn(v.x, v.y);
            half2 p1 = __floats2half2_rn(v.z, v.w);
            uint2 w;
            w.x = *(const u32*)&p0;
            w.y = *(const u32*)&p1;
            *(uint2*)&gout[(size_t)grow * HID + c4] = w;
        }
    }
}

// ---------------- layer-2 GEMM (fused layer-1 linear): Ah = relu(XA@W1+b1) @ W2 ----------------
__global__ __launch_bounds__(256) void k_gemm_l2(const float* __restrict__ W1,
                                                 const float* __restrict__ b1,
                                                 const float* __restrict__ W2) {
    extern __shared__ char shc[];
    __half* Wh  = (__half*)shc;                       // [128][136] W2 hi
    __half* Wl  = Wh + HID * W_PITCH;                 // [128][136] W2 lo
    __half* At  = Wl + HID * W_PITCH;                 // [128][136] input tile
    float*  W1s = (float*)(At + TILE_ROWS * A_PITCH); // [5][128]
    float*  b1s = W1s + 5 * HID;                      // [128]
    int tid = threadIdx.x;

    load_split_W(Wh, Wl, W2, tid);
    for (int i = tid; i < 5 * HID; i += 256) W1s[i] = W1[i];
    if (tid < HID) b1s[tid] = b1[tid];
    __syncthreads();

    int warp = tid >> 5, lane = tid & 31;
    int row0 = blockIdx.x * TILE_ROWS;

    // prologue: relu(XA@W1 + b1) -> At (fp32 math, fp16 store); warp handles 16 rows
    {
        float4 w1v[5];
        #pragma unroll
        for (int k = 0; k < 5; k++) w1v[k] = ((const float4*)(W1s + k * HID))[lane];
        float4 b1v = ((const float4*)b1s)[lane];
        #pragma unroll
        for (int rr = 0; rr < 16; rr++) {
            int node = row0 + warp * 16 + rr;
            float4 h = make_float4(0.f, 0.f, 0.f, 0.f);
            if (node < N_NODES) {
                const float* xa = g_XA + (size_t)node * 5;
                float xk[5];
                #pragma unroll
                for (int k = 0; k < 5; k++) xk[k] = xa[k];
                h = b1v;
                #pragma unroll
                for (int k = 0; k < 5; k++) {
                    h.x = fmaf(xk[k], w1v[k].x, h.x);
                    h.y = fmaf(xk[k], w1v[k].y, h.y);
                    h.z = fmaf(xk[k], w1v[k].z, h.z);
                    h.w = fmaf(xk[k], w1v[k].w, h.w);
                }
                h.x = fmaxf(h.x, 0.f); h.y = fmaxf(h.y, 0.f);
                h.z = fmaxf(h.z, 0.f); h.w = fmaxf(h.w, 0.f);
            }
            __half* dp = At + (warp * 16 + rr) * A_PITCH + lane * 4;
            *(half2*)dp       = __floats2half2_rn(h.x, h.y);
            *(half2*)(dp + 2) = __floats2half2_rn(h.z, h.w);
        }
    }
    __syncthreads();

    mma_tile_and_store(Wh, Wl, At, (float*)Wh, g_Ah, row0, tid);
}

// ---------------- layer-3 GEMM: Ah = relu(Bh) @ W3  (split-W HMMA) ----------------
__global__ __launch_bounds__(256) void k_gemm_l3(const float* __restrict__ W3) {
    extern __shared__ char shc[];
    __half* Wh = (__half*)shc;                        // [128][136] hi
    __half* Wl = Wh + HID * W_PITCH;                  // [128][136] lo
    __half* At = Wl + HID * W_PITCH;                  // [128][136]
    int tid = threadIdx.x;

    load_split_W(Wh, Wl, W3, tid);

    int row0 = blockIdx.x * TILE_ROWS;
    // tile load: relu(Bh) -> At: 128 rows x 16 uint4 (8 halves each)
    half2 z2 = __floats2half2_rn(0.f, 0.f);
    #pragma unroll
    for (int i = 0; i < 8; i++) {
        int li = tid + 256 * i;               // 0..2047: r = li>>4, q = li&15
        int r = li >> 4, q = li & 15;
        int grow = row0 + r;
        uint4 v = make_uint4(0u, 0u, 0u, 0u);
        if (grow < N_NODES) v = *(const uint4*)&g_Bh[(size_t)grow * HID + q * 8];
        half2 h0 = __hmax2(*(half2*)&v.x, z2);
        half2 h1 = __hmax2(*(half2*)&v.y, z2);
        half2 h2 = __hmax2(*(half2*)&v.z, z2);
        half2 h3 = __hmax2(*(half2*)&v.w, z2);
        __half* dp = At + r * A_PITCH + q * 8;
        *(half2*)(dp + 0) = h0;
        *(half2*)(dp + 2) = h1;
        *(half2*)(dp + 4) = h2;
        *(half2*)(dp + 6) = h3;
    }
    __syncthreads();

    mma_tile_and_store(Wh, Wl, At, (float*)Wh, g_Ah, row0, tid);
}

// ---------------- layer-3 aggregation fused with final FC (fp16 gather, fp32 math) ----------------
__global__ __launch_bounds__(256) void k_agg_final(const float* __restrict__ bias,
                                                   const float* __restrict__ Wfc,
                                                   const float* __restrict__ bfc,
                                                   float* __restrict__ out) {
    int g = blockIdx.x * blockDim.x + threadIdx.x;
    int node = g >> 5;
    int lane = g & 31;
    if (node >= N_NODES) return;

    const uint2* __restrict__ A2 = (const uint2*)g_Ah;
    float dv = g_dinv[node];
    uint2 raw = A2[(size_t)node * 32 + lane];
    float2 s0 = __half22float2(*(const half2*)&raw.x);
    float2 s1 = __half22float2(*(const half2*)&raw.y);
    float4 acc;
    acc.x = dv * s0.x; acc.y = dv * s0.y; acc.z = dv * s1.x; acc.w = dv * s1.y;

    int cnt = g_cnt[node];
    int start = g_off[node] - cnt;
    for (int j0 = 0; j0 < cnt; j0 += 32) {
        int  rem = cnt - j0;
        bool ok  = lane < rem;
        uint2 ev = ok ? g_edge[start + j0 + lane] : make_uint2(0u, 0u);
        int m = min(32, rem);
        #pragma unroll 8
        for (int j = 0; j < m; j++) {
            int   sj = (int)__shfl_sync(0xffffffffu, ev.x, j);
            float wj = __uint_as_float(__shfl_sync(0xffffffffu, ev.y, j));
            uint2 r = A2[(size_t)sj * 32 + lane];
            float2 f0 = __half22float2(*(const half2*)&r.x);
            float2 f1 = __half22float2(*(const half2*)&r.y);
            acc.x = fmaf(wj, f0.x, acc.x);
            acc.y = fmaf(wj, f0.y, acc.y);
            acc.z = fmaf(wj, f1.x, acc.z);
            acc.w = fmaf(wj, f1.y, acc.w);
        }
    }
    float4 bb = ((const float4*)bias)[lane];
    float4 w  = ((const float4*)Wfc)[lane];
    float dot = fmaxf(fmaf(dv, acc.x, bb.x), 0.f) * w.x
              + fmaxf(fmaf(dv, acc.y, bb.y), 0.f) * w.y
              + fmaxf(fmaf(dv, acc.z, bb.z), 0.f) * w.z
              + fmaxf(fmaf(dv, acc.w, bb.w), 0.f) * w.w;
    #pragma unroll
    for (int o = 16; o > 0; o >>= 1) dot += __shfl_xor_sync(0xffffffffu, dot, o);
    if (lane == 0) out[node] = dot + bfc[0];
}

// ---------------- launcher ----------------
extern "C" void kernel_launch(void* const* d_in, const int* in_sizes, int n_in,
                              void* d_out, int out_size) {
    const float* x   = (const float*)d_in[0];
    const int*   ei  = (const int*)  d_in[1];
    const float* W1  = (const float*)d_in[2];
    const float* b1  = (const float*)d_in[3];
    const float* W2  = (const float*)d_in[4];
    const float* b2  = (const float*)d_in[5];
    const float* W3  = (const float*)d_in[6];
    const float* b3  = (const float*)d_in[7];
    const float* Wfc = (const float*)d_in[8];
    const float* bfc = (const float*)d_in[9];
    float* out = (float*)d_out;

    const int* src = ei;
    const int* dst = ei + N_EDGES;

    cudaFuncSetAttribute(k_gemm_l2, cudaFuncAttributeMaxDynamicSharedMemorySize, L2_SMEM);
    cudaFuncSetAttribute(k_gemm_l3, cudaFuncAttributeMaxDynamicSharedMemorySize, L3_SMEM);

    const int T = 256;
    int nb_warps = (N_NODES * 32 + T - 1) / T;
    int nb_gemm  = (N_NODES + TILE_ROWS - 1) / TILE_ROWS;

    // reset global-barrier counters (graph-capturable, no alloc)
    void* barPtr = nullptr;
    cudaGetSymbolAddress(&barPtr, g_barc);
    cudaMemsetAsync(barPtr, 0, sizeof(u32) * 8);

    // fused CSR build + agg_x (persistent, device-side barriers)
    k_csr<<<NCTA, CSR_T>>>(src, dst, x);

    // pipeline
    k_gemm_l2 <<<nb_gemm, T, L2_SMEM>>>(W1, b1, W2);   // Ah = relu(XA@W1+b1) @ W2  (split-W HMMA)
    k_agg     <<<nb_warps, T>>>(b2);                    // Bh = Â·Ah + b2
    k_gemm_l3 <<<nb_gemm, T, L3_SMEM>>>(W3);            // Ah = relu(Bh) @ W3        (split-W HMMA)
    k_agg_final<<<nb_warps, T>>>(b3, Wfc, bfc, out);    // out = relu(Â·Ah+b3)·Wfc + bfc
}

// round 15
// speedup vs baseline: 1.0751x; 1.0751x over previous
#include <cuda_runtime.h>
#include <cuda_fp16.h>
#include <mma.h>
using namespace nvcuda;

#define N_NODES 100000
#define N_EDGES 1600000
#define HID 128
#define SCAN_B 1024
#define NB_SCAN ((N_NODES + SCAN_B - 1) / SCAN_B)   // 98

typedef unsigned long long u64;
typedef unsigned int u32;

// Scratch (no cudaMalloc allowed). Features stored fp16 (aggregation math fp32).
__device__ __align__(16) __half g_Ah[(size_t)N_NODES * HID];  // GEMM outputs / message source
__device__ __align__(16) __half g_Bh[(size_t)N_NODES * HID];  // aggregated features
__device__ __align__(16) float  g_XA[(size_t)N_NODES * 5];    // aggregated raw input (fp32)
__device__ __align__(16) float  g_dinv[N_NODES];
__device__ int   g_cnt[N_NODES];
__device__ int   g_off[N_NODES];     // scan result; k_fill bumps it to segment END
__device__ int   g_bsum[NB_SCAN];
__device__ __align__(8) uint2 g_edge[N_EDGES];   // (src, dinv[src] bits) interleaved

// ---------------- CSR build ----------------
__global__ void k_deg_count(const int* __restrict__ dst) {
    int e = blockIdx.x * blockDim.x + threadIdx.x;
    if (e < N_EDGES) atomicAdd(&g_cnt[dst[e]], 1);
}

// per-block sums of g_cnt + fused dinv computation
__global__ __launch_bounds__(SCAN_B) void k_bsum() {
    __shared__ int sh[SCAN_B];
    int t = threadIdx.x;
    int i = blockIdx.x * SCAN_B + t;
    int c = 0;
    if (i < N_NODES) {
        c = g_cnt[i];
        g_dinv[i] = rsqrtf((float)(c + 1));   // +1 self loop
    }
    sh[t] = c;
    __syncthreads();
    #pragma unroll
    for (int off = SCAN_B / 2; off > 0; off >>= 1) {
        if (t < off) sh[t] += sh[t + off];
        __syncthreads();
    }
    if (t == 0) g_bsum[blockIdx.x] = sh[0];
}

// in-block exclusive scan + inline prefix of block sums (merged bscan)
__global__ __launch_bounds__(SCAN_B) void k_boff() {
    __shared__ int sh[SCAN_B];
    __shared__ int base;
    int t = threadIdx.x;
    if (t < 32) {
        int s = 0;
        for (int i = t; i < (int)blockIdx.x; i += 32) s += g_bsum[i];
        #pragma unroll
        for (int o = 16; o > 0; o >>= 1) s += __shfl_xor_sync(0xffffffffu, s, o);
        if (t == 0) base = s;
    }
    int i = blockIdx.x * SCAN_B + t;
    int v = (i < N_NODES) ? g_cnt[i] : 0;
    sh[t] = v;
    __syncthreads();
    #pragma unroll
    for (int off = 1; off < SCAN_B; off <<= 1) {
        int cur = sh[t];
        int a = (t >= off) ? sh[t - off] : 0;
        __syncthreads();
        sh[t] = cur + a;
        __syncthreads();
    }
    if (i < N_NODES) g_off[i] = base + sh[t] - v;   // exclusive
}

// destructive fill: g_off[d] ends at segment END; start recovered as end - cnt
// 2 edges per thread, int2 index loads, single 8-byte interleaved store per edge
__global__ void k_fill(const int* __restrict__ src, const int* __restrict__ dst) {
    int p = blockIdx.x * blockDim.x + threadIdx.x;
    int e0 = p * 2;
    if (e0 >= N_EDGES) return;
    int2 sv = *(const int2*)(src + e0);
    int2 dv = *(const int2*)(dst + e0);
    {
        int pos = atomicAdd(&g_off[dv.x], 1);
        uint2 ev; ev.x = (u32)sv.x; ev.y = __float_as_uint(g_dinv[sv.x]);
        g_edge[pos] = ev;
    }
    {
        int pos = atomicAdd(&g_off[dv.y], 1);
        uint2 ev; ev.x = (u32)sv.y; ev.y = __float_as_uint(g_dinv[sv.y]);
        g_edge[pos] = ev;
    }
}

// ---------------- layer-1 input aggregation: XA = Â X  (5-wide, fp32) ----------------
__global__ __launch_bounds__(256) void k_agg_x(const float* __restrict__ x) {
    int i = blockIdx.x * blockDim.x + threadIdx.x;
    if (i >= N_NODES) return;
    float dv = g_dinv[i];
    float acc[5];
    #pragma unroll
    for (int k = 0; k < 5; k++) acc[k] = dv * x[(size_t)i * 5 + k];
    int cnt = g_cnt[i];
    int start = g_off[i] - cnt;
    for (int j = 0; j < cnt; j++) {
        uint2 ev = g_edge[start + j];
        int s = (int)ev.x;
        float w = __uint_as_float(ev.y);
        #pragma unroll
        for (int k = 0; k < 5; k++) acc[k] = fmaf(w, x[(size_t)s * 5 + k], acc[k]);
    }
    #pragma unroll
    for (int k = 0; k < 5; k++) g_XA[(size_t)i * 5 + k] = dv * acc[k];
}

// ---------------- aggregation: Bh = Â·Ah + bias  (warp/node; fp16 in/out, fp32 math) ----------------
__global__ __launch_bounds__(256) void k_agg(const float* __restrict__ bias) {
    int g = blockIdx.x * blockDim.x + threadIdx.x;
    int node = g >> 5;
    int lane = g & 31;
    if (node >= N_NODES) return;

    const uint2* __restrict__ A2 = (const uint2*)g_Ah;   // 4 halves per uint2; 32 uint2 per row
    float dv = g_dinv[node];
    uint2 raw = A2[(size_t)node * 32 + lane];
    float2 s0 = __half22float2(*(const half2*)&raw.x);
    float2 s1 = __half22float2(*(const half2*)&raw.y);
    float4 acc;
    acc.x = dv * s0.x; acc.y = dv * s0.y; acc.z = dv * s1.x; acc.w = dv * s1.y;

    int cnt = g_cnt[node];
    int start = g_off[node] - cnt;
    for (int j0 = 0; j0 < cnt; j0 += 32) {
        int  rem = cnt - j0;
        bool ok  = lane < rem;
        uint2 ev = ok ? g_edge[start + j0 + lane] : make_uint2(0u, 0u);
        int m = min(32, rem);
        #pragma unroll 8
        for (int j = 0; j < m; j++) {
            int   sj = (int)__shfl_sync(0xffffffffu, ev.x, j);
            float wj = __uint_as_float(__shfl_sync(0xffffffffu, ev.y, j));
            uint2 r = A2[(size_t)sj * 32 + lane];
            float2 f0 = __half22float2(*(const half2*)&r.x);
            float2 f1 = __half22float2(*(const half2*)&r.y);
            acc.x = fmaf(wj, f0.x, acc.x);
            acc.y = fmaf(wj, f0.y, acc.y);
            acc.z = fmaf(wj, f1.x, acc.z);
            acc.w = fmaf(wj, f1.y, acc.w);
        }
    }
    float4 bb = ((const float4*)bias)[lane];
    float2 o0, o1;
    o0.x = fmaf(dv, acc.x, bb.x);
    o0.y = fmaf(dv, acc.y, bb.y);
    o1.x = fmaf(dv, acc.z, bb.z);
    o1.y = fmaf(dv, acc.w, bb.w);
    half2 p0 = __float22half2_rn(o0);
    half2 p1 = __float22half2_rn(o1);
    uint2 w;
    w.x = *(const u32*)&p0;
    w.y = *(const u32*)&p1;
    ((uint2*)g_Bh)[(size_t)node * 32 + lane] = w;
}

// ---------------- tensor-core GEMM layout constants (128-row CTA tiles) ----------------
#define TILE_ROWS 128
#define A_PITCH 136              // halves (272 B rows)
#define W_PITCH 136
#define SC_PITCH 132             // floats
#define WH_BYTES (HID * W_PITCH * 2)            // 34816 (one W plane)
#define AT_BYTES (TILE_ROWS * A_PITCH * 2)      // 34816
#define L2_SMEM (2 * WH_BYTES + AT_BYTES + (5 * HID + HID) * 4)  // 107008 B
#define L3_SMEM (2 * WH_BYTES + AT_BYTES)                        // 104448 B

// split a float into hi/lo halves: w = hi + lo with |lo| <~ w*2^-12
__device__ __forceinline__ void split_h(float v, __half& hi, __half& lo) {
    hi = __float2half_rn(v);
    lo = __float2half_rn(v - __half2float(hi));
}

__device__ __forceinline__ void load_split_W(__half* Wh, __half* Wl,
                                             const float* __restrict__ W, int tid) {
    const float4* W4 = (const float4*)W;
    #pragma unroll
    for (int i = 0; i < 16; i++) {
        int idx4 = tid + 256 * i;                     // 0..4095
        int k = idx4 >> 5, c0 = (idx4 & 31) * 4;
        float4 v = W4[idx4];
        __half h0, l0, h1, l1, h2, l2, h3, l3;
        split_h(v.x, h0, l0); split_h(v.y, h1, l1);
        split_h(v.z, h2, l2); split_h(v.w, h3, l3);
        __half* wp = Wh + k * W_PITCH + c0;
        wp[0] = h0; wp[1] = h1; wp[2] = h2; wp[3] = h3;
        __half* lp = Wl + k * W_PITCH + c0;
        lp[0] = l0; lp[1] = l1; lp[2] = l2; lp[3] = l3;
    }
}

// shared mainloop + epilogue.
// Warp tile 32 rows x 64 cols: warp w -> rows [(w&3)*32, +32), cols [(w>>2)*64, +64).
// Halves per-warp W smem traffic vs 16x128 tiling (W bytes/warp: 64KB -> 32KB).
__device__ __forceinline__ void mma_tile_and_store(const __half* Wh, const __half* Wl,
                                                   const __half* At, float* sc,
                                                   __half* gout, int row0, int tid) {
    int warp = tid >> 5;
    int rt = warp & 3;        // row subtile (32 rows)
    int ct = warp >> 2;       // col half (64 cols)
    wmma::fragment<wmma::accumulator, 16, 16, 16, float> fc[2][4];
    #pragma unroll
    for (int a = 0; a < 2; a++)
        #pragma unroll
        for (int j = 0; j < 4; j++) wmma::fill_fragment(fc[a][j], 0.0f);
    #pragma unroll
    for (int k0 = 0; k0 < 8; k0++) {
        wmma::fragment<wmma::matrix_a, 16, 16, 16, __half, wmma::row_major> fa0, fa1;
        wmma::load_matrix_sync(fa0, At + (rt * 32 + 0)  * A_PITCH + k0 * 16, A_PITCH);
        wmma::load_matrix_sync(fa1, At + (rt * 32 + 16) * A_PITCH + k0 * 16, A_PITCH);
        #pragma unroll
        for (int j = 0; j < 4; j++) {
            wmma::fragment<wmma::matrix_b, 16, 16, 16, __half, wmma::row_major> fb;
            wmma::load_matrix_sync(fb, Wh + k0 * 16 * W_PITCH + ct * 64 + j * 16, W_PITCH);
            wmma::mma_sync(fc[0][j], fa0, fb, fc[0][j]);
            wmma::mma_sync(fc[1][j], fa1, fb, fc[1][j]);
            wmma::load_matrix_sync(fb, Wl + k0 * 16 * W_PITCH + ct * 64 + j * 16, W_PITCH);
            wmma::mma_sync(fc[0][j], fa0, fb, fc[0][j]);
            wmma::mma_sync(fc[1][j], fa1, fb, fc[1][j]);
        }
    }
    __syncthreads();          // done reading W planes; reuse Wh+Wl (69632 B) as fp32 scratch
    #pragma unroll
    for (int a = 0; a < 2; a++)
        #pragma unroll
        for (int j = 0; j < 4; j++)
            wmma::store_matrix_sync(sc + (rt * 32 + a * 16) * SC_PITCH + ct * 64 + j * 16,
                                    fc[a][j], SC_PITCH, wmma::mem_row_major);
    __syncthreads();
    // convert scratch -> gout (fp16): 128 rows x 32 col-quads, uint2 stores
    #pragma unroll
    for (int i = 0; i < 16; i++) {
        int li = tid + 256 * i;               // 0..4095
        int r = li >> 5, c4 = (li & 31) * 4;
        int grow = row0 + r;
        if (grow < N_NODES) {
            float4 v = *(float4*)&sc[r * SC_PITCH + c4];
            half2 p0 = __floats2half2_rn(v.x, v.y);
            half2 p1 = __floats2half2_rn(v.z, v.w);
            uint2 w;
            w.x = *(const u32*)&p0;
            w.y = *(const u32*)&p1;
            *(uint2*)&gout[(size_t)grow * HID + c4] = w;
        }
    }
}

// ---------------- layer-2 GEMM (fused layer-1 linear): Ah = relu(XA@W1+b1) @ W2 ----------------
__global__ __launch_bounds__(256) void k_gemm_l2(const float* __restrict__ W1,
                                                 const float* __restrict__ b1,
                                                 const float* __restrict__ W2) {
    extern __shared__ char shc[];
    __half* Wh  = (__half*)shc;                       // [128][136] W2 hi
    __half* Wl  = Wh + HID * W_PITCH;                 // [128][136] W2 lo
    __half* At  = Wl + HID * W_PITCH;                 // [128][136] input tile
    float*  W1s = (float*)(At + TILE_ROWS * A_PITCH); // [5][128]
    float*  b1s = W1s + 5 * HID;                      // [128]
    int tid = threadIdx.x;

    load_split_W(Wh, Wl, W2, tid);
    for (int i = tid; i < 5 * HID; i += 256) W1s[i] = W1[i];
    if (tid < HID) b1s[tid] = b1[tid];
    __syncthreads();

    int warp = tid >> 5, lane = tid & 31;
    int row0 = blockIdx.x * TILE_ROWS;

    // prologue: relu(XA@W1 + b1) -> At (fp32 math, fp16 store); warp handles 16 rows
    {
        float4 w1v[5];
        #pragma unroll
        for (int k = 0; k < 5; k++) w1v[k] = ((const float4*)(W1s + k * HID))[lane];
        float4 b1v = ((const float4*)b1s)[lane];
        #pragma unroll
        for (int rr = 0; rr < 16; rr++) {
            int node = row0 + warp * 16 + rr;
            float4 h = make_float4(0.f, 0.f, 0.f, 0.f);
            if (node < N_NODES) {
                const float* xa = g_XA + (size_t)node * 5;
                float xk[5];
                #pragma unroll
                for (int k = 0; k < 5; k++) xk[k] = xa[k];
                h = b1v;
                #pragma unroll
                for (int k = 0; k < 5; k++) {
                    h.x = fmaf(xk[k], w1v[k].x, h.x);
                    h.y = fmaf(xk[k], w1v[k].y, h.y);
                    h.z = fmaf(xk[k], w1v[k].z, h.z);
                    h.w = fmaf(xk[k], w1v[k].w, h.w);
                }
                h.x = fmaxf(h.x, 0.f); h.y = fmaxf(h.y, 0.f);
                h.z = fmaxf(h.z, 0.f); h.w = fmaxf(h.w, 0.f);
            }
            __half* dp = At + (warp * 16 + rr) * A_PITCH + lane * 4;
            *(half2*)dp       = __floats2half2_rn(h.x, h.y);
            *(half2*)(dp + 2) = __floats2half2_rn(h.z, h.w);
        }
    }
    __syncthreads();

    mma_tile_and_store(Wh, Wl, At, (float*)Wh, g_Ah, row0, tid);
}

// ---------------- layer-3 GEMM: Ah = relu(Bh) @ W3  (split-W HMMA) ----------------
__global__ __launch_bounds__(256) void k_gemm_l3(const float* __restrict__ W3) {
    extern __shared__ char shc[];
    __half* Wh = (__half*)shc;                        // [128][136] hi
    __half* Wl = Wh + HID * W_PITCH;                  // [128][136] lo
    __half* At = Wl + HID * W_PITCH;                  // [128][136]
    int tid = threadIdx.x;

    load_split_W(Wh, Wl, W3, tid);

    int row0 = blockIdx.x * TILE_ROWS;
    // tile load: relu(Bh) -> At: 128 rows x 16 uint4 (8 halves each)
    half2 z2 = __floats2half2_rn(0.f, 0.f);
    #pragma unroll
    for (int i = 0; i < 8; i++) {
        int li = tid + 256 * i;               // 0..2047: r = li>>4, q = li&15
        int r = li >> 4, q = li & 15;
        int grow = row0 + r;
        uint4 v = make_uint4(0u, 0u, 0u, 0u);
        if (grow < N_NODES) v = *(const uint4*)&g_Bh[(size_t)grow * HID + q * 8];
        half2 h0 = __hmax2(*(half2*)&v.x, z2);
        half2 h1 = __hmax2(*(half2*)&v.y, z2);
        half2 h2 = __hmax2(*(half2*)&v.z, z2);
        half2 h3 = __hmax2(*(half2*)&v.w, z2);
        __half* dp = At + r * A_PITCH + q * 8;
        *(half2*)(dp + 0) = h0;
        *(half2*)(dp + 2) = h1;
        *(half2*)(dp + 4) = h2;
        *(half2*)(dp + 6) = h3;
    }
    __syncthreads();

    mma_tile_and_store(Wh, Wl, At, (float*)Wh, g_Ah, row0, tid);
}

// ---------------- layer-3 aggregation fused with final FC (fp16 gather, fp32 math) ----------------
__global__ __launch_bounds__(256) void k_agg_final(const float* __restrict__ bias,
                                                   const float* __restrict__ Wfc,
                                                   const float* __restrict__ bfc,
                                                   float* __restrict__ out) {
    int g = blockIdx.x * blockDim.x + threadIdx.x;
    int node = g >> 5;
    int lane = g & 31;
    if (node >= N_NODES) return;

    const uint2* __restrict__ A2 = (const uint2*)g_Ah;
    float dv = g_dinv[node];
    uint2 raw = A2[(size_t)node * 32 + lane];
    float2 s0 = __half22float2(*(const half2*)&raw.x);
    float2 s1 = __half22float2(*(const half2*)&raw.y);
    float4 acc;
    acc.x = dv * s0.x; acc.y = dv * s0.y; acc.z = dv * s1.x; acc.w = dv * s1.y;

    int cnt = g_cnt[node];
    int start = g_off[node] - cnt;
    for (int j0 = 0; j0 < cnt; j0 += 32) {
        int  rem = cnt - j0;
        bool ok  = lane < rem;
        uint2 ev = ok ? g_edge[start + j0 + lane] : make_uint2(0u, 0u);
        int m = min(32, rem);
        #pragma unroll 8
        for (int j = 0; j < m; j++) {
            int   sj = (int)__shfl_sync(0xffffffffu, ev.x, j);
            float wj = __uint_as_float(__shfl_sync(0xffffffffu, ev.y, j));
            uint2 r = A2[(size_t)sj * 32 + lane];
            float2 f0 = __half22float2(*(const half2*)&r.x);
            float2 f1 = __half22float2(*(const half2*)&r.y);
            acc.x = fmaf(wj, f0.x, acc.x);
            acc.y = fmaf(wj, f0.y, acc.y);
            acc.z = fmaf(wj, f1.x, acc.z);
            acc.w = fmaf(wj, f1.y, acc.w);
        }
    }
    float4 bb = ((const float4*)bias)[lane];
    float4 w  = ((const float4*)Wfc)[lane];
    float dot = fmaxf(fmaf(dv, acc.x, bb.x), 0.f) * w.x
              + fmaxf(fmaf(dv, acc.y, bb.y), 0.f) * w.y
              + fmaxf(fmaf(dv, acc.z, bb.z), 0.f) * w.z
              + fmaxf(fmaf(dv, acc.w, bb.w), 0.f) * w.w;
    #pragma unroll
    for (int o = 16; o > 0; o >>= 1) dot += __shfl_xor_sync(0xffffffffu, dot, o);
    if (lane == 0) out[node] = dot + bfc[0];
}

// ---------------- launcher ----------------
extern "C" void kernel_launch(void* const* d_in, const int* in_sizes, int n_in,
                              void* d_out, int out_size) {
    const float* x   = (const float*)d_in[0];
    const int*   ei  = (const int*)  d_in[1];
    const float* W1  = (const float*)d_in[2];
    const float* b1  = (const float*)d_in[3];
    const float* W2  = (const float*)d_in[4];
    const float* b2  = (const float*)d_in[5];
    const float* W3  = (const float*)d_in[6];
    const float* b3  = (const float*)d_in[7];
    const float* Wfc = (const float*)d_in[8];
    const float* bfc = (const float*)d_in[9];
    float* out = (float*)d_out;

    const int* src = ei;
    const int* dst = ei + N_EDGES;

    cudaFuncSetAttribute(k_gemm_l2, cudaFuncAttributeMaxDynamicSharedMemorySize, L2_SMEM);
    cudaFuncSetAttribute(k_gemm_l3, cudaFuncAttributeMaxDynamicSharedMemorySize, L3_SMEM);

    const int T = 256;
    int nb_nodes = (N_NODES + T - 1) / T;
    int nb_edges = (N_EDGES + T - 1) / T;
    int nb_fill  = (N_EDGES / 2 + T - 1) / T;
    int nb_warps = (N_NODES * 32 + T - 1) / T;
    int nb_gemm  = (N_NODES + TILE_ROWS - 1) / TILE_ROWS;

    // CSR build (g_cnt zeroed via async memset — graph-capturable, no alloc)
    void* cntPtr = nullptr;
    cudaGetSymbolAddress(&cntPtr, g_cnt);
    cudaMemsetAsync(cntPtr, 0, N_NODES * sizeof(int));
    k_deg_count<<<nb_edges, T>>>(dst);
    k_bsum     <<<NB_SCAN, SCAN_B>>>();
    k_boff     <<<NB_SCAN, SCAN_B>>>();
    k_fill     <<<nb_fill, T>>>(src, dst);

    // pipeline
    k_agg_x   <<<nb_nodes, T>>>(x);
    k_gemm_l2 <<<nb_gemm, T, L2_SMEM>>>(W1, b1, W2);   // Ah = relu(XA@W1+b1) @ W2  (split-W HMMA)
    k_agg     <<<nb_warps, T>>>(b2);                    // Bh = Â·Ah + b2
    k_gemm_l3 <<<nb_gemm, T, L3_SMEM>>>(W3);            // Ah = relu(Bh) @ W3        (split-W HMMA)
    k_agg_final<<<nb_warps, T>>>(b3, Wfc, bfc, out);    // out = relu(Â·Ah+b3)·Wfc + bfc
}

// round 17
// speedup vs baseline: 1.1370x; 1.0576x over previous
#include <cuda_runtime.h>
#include <cuda_fp16.h>
#include <mma.h>
using namespace nvcuda;

#define N_NODES 100000
#define N_EDGES 1600000
#define HID 128
#define SCAN_B 1024
#define NB_SCAN ((N_NODES + SCAN_B - 1) / SCAN_B)   // 98

typedef unsigned long long u64;
typedef unsigned int u32;

// Scratch (no cudaMalloc allowed). Features stored fp16 PRE-SCALED by dinv[row].
__device__ __align__(16) __half g_Ah[(size_t)N_NODES * HID];  // scaled GEMM outputs
__device__ __align__(16) __half g_Bh[(size_t)N_NODES * HID];  // aggregated features (pre-act)
__device__ __align__(16) float  g_XA[(size_t)N_NODES * 5];    // aggregated raw input (fp32)
__device__ __align__(16) float  g_xs[(size_t)N_NODES * 5];    // dinv[i]*x[i] (scaled input)
__device__ __align__(16) float  g_dinv[N_NODES];
__device__ int   g_cnt[N_NODES];
__device__ int   g_off[N_NODES];     // scan result; k_fill bumps it to segment END
__device__ int   g_bsum[NB_SCAN];
__device__ int   g_esrc[N_EDGES];    // CSR: src node per slot (4B records, no weight)

// ---------------- CSR build ----------------
__global__ void k_deg_count(const int* __restrict__ dst) {
    int p = blockIdx.x * blockDim.x + threadIdx.x;
    int e0 = p * 2;
    if (e0 >= N_EDGES) return;
    int2 dv = *(const int2*)(dst + e0);
    atomicAdd(&g_cnt[dv.x], 1);
    atomicAdd(&g_cnt[dv.y], 1);
}

// per-block sums of g_cnt + fused dinv + scaled-input xs = dinv*x
__global__ __launch_bounds__(SCAN_B) void k_bsum(const float* __restrict__ x) {
    __shared__ int sh[SCAN_B];
    int t = threadIdx.x;
    int i = blockIdx.x * SCAN_B + t;
    int c = 0;
    if (i < N_NODES) {
        c = g_cnt[i];
        float dv = rsqrtf((float)(c + 1));   // +1 self loop
        g_dinv[i] = dv;
        const float* xr = x + (size_t)i * 5;
        float* xo = g_xs + (size_t)i * 5;
        #pragma unroll
        for (int k = 0; k < 5; k++) xo[k] = dv * xr[k];
    }
    sh[t] = c;
    __syncthreads();
    #pragma unroll
    for (int off = SCAN_B / 2; off > 0; off >>= 1) {
        if (t < off) sh[t] += sh[t + off];
        __syncthreads();
    }
    if (t == 0) g_bsum[blockIdx.x] = sh[0];
}

// in-block exclusive scan + inline prefix of block sums
__global__ __launch_bounds__(SCAN_B) void k_boff() {
    __shared__ int sh[SCAN_B];
    __shared__ int base;
    int t = threadIdx.x;
    if (t < 32) {
        int s = 0;
        for (int i = t; i < (int)blockIdx.x; i += 32) s += g_bsum[i];
        #pragma unroll
        for (int o = 16; o > 0; o >>= 1) s += __shfl_xor_sync(0xffffffffu, s, o);
        if (t == 0) base = s;
    }
    int i = blockIdx.x * SCAN_B + t;
    int v = (i < N_NODES) ? g_cnt[i] : 0;
    sh[t] = v;
    __syncthreads();
    #pragma unroll
    for (int off = 1; off < SCAN_B; off <<= 1) {
        int cur = sh[t];
        int a = (t >= off) ? sh[t - off] : 0;
        __syncthreads();
        sh[t] = cur + a;
        __syncthreads();
    }
    if (i < N_NODES) g_off[i] = base + sh[t] - v;   // exclusive
}

// destructive fill: g_off[d] ends at segment END; start recovered as end - cnt
// 2 edges per thread; 4-byte src-only records (weight folded into stored features)
__global__ void k_fill(const int* __restrict__ src, const int* __restrict__ dst) {
    int p = blockIdx.x * blockDim.x + threadIdx.x;
    int e0 = p * 2;
    if (e0 >= N_EDGES) return;
    int2 sv = *(const int2*)(src + e0);
    int2 dv = *(const int2*)(dst + e0);
    int pos0 = atomicAdd(&g_off[dv.x], 1);
    g_esrc[pos0] = sv.x;
    int pos1 = atomicAdd(&g_off[dv.y], 1);
    g_esrc[pos1] = sv.y;
}

// ---------------- layer-1 input aggregation: XA = Â X  (5-wide, fp32) ----------------
// XA[i] = dinv[i] * ( sum_e xs[src] + xs[i] )   with xs = dinv*x
__global__ __launch_bounds__(256) void k_agg_x() {
    int i = blockIdx.x * blockDim.x + threadIdx.x;
    if (i >= N_NODES) return;
    float dv = g_dinv[i];
    float acc[5];
    const float* xr = g_xs + (size_t)i * 5;
    #pragma unroll
    for (int k = 0; k < 5; k++) acc[k] = xr[k];
    int cnt = g_cnt[i];
    int start = g_off[i] - cnt;
    for (int j = 0; j < cnt; j++) {
        int s = g_esrc[start + j];
        const float* xsr = g_xs + (size_t)s * 5;
        #pragma unroll
        for (int k = 0; k < 5; k++) acc[k] += xsr[k];
    }
    #pragma unroll
    for (int k = 0; k < 5; k++) g_XA[(size_t)i * 5 + k] = dv * acc[k];
}

// ---------------- aggregation: Bh = dinv*(sum Ah[src] + Ah[node]) + bias ----------------
__global__ __launch_bounds__(256) void k_agg(const float* __restrict__ bias) {
    int g = blockIdx.x * blockDim.x + threadIdx.x;
    int node = g >> 5;
    int lane = g & 31;
    if (node >= N_NODES) return;

    const uint2* __restrict__ A2 = (const uint2*)g_Ah;   // 4 halves per uint2
    float dv = g_dinv[node];
    uint2 raw = A2[(size_t)node * 32 + lane];
    float2 s0 = __half22float2(*(const half2*)&raw.x);
    float2 s1 = __half22float2(*(const half2*)&raw.y);
    float4 acc;
    acc.x = s0.x; acc.y = s0.y; acc.z = s1.x; acc.w = s1.y;

    int cnt = g_cnt[node];
    int start = g_off[node] - cnt;
    for (int j0 = 0; j0 < cnt; j0 += 32) {
        int  rem = cnt - j0;
        bool ok  = lane < rem;
        int  sv  = ok ? g_esrc[start + j0 + lane] : 0;
        int m = min(32, rem);
        #pragma unroll 8
        for (int j = 0; j < m; j++) {
            int sj = __shfl_sync(0xffffffffu, sv, j);
            uint2 r = A2[(size_t)sj * 32 + lane];
            float2 f0 = __half22float2(*(const half2*)&r.x);
            float2 f1 = __half22float2(*(const half2*)&r.y);
            acc.x += f0.x; acc.y += f0.y;
            acc.z += f1.x; acc.w += f1.y;
        }
    }
    float4 bb = ((const float4*)bias)[lane];
    float2 o0, o1;
    o0.x = fmaf(dv, acc.x, bb.x);
    o0.y = fmaf(dv, acc.y, bb.y);
    o1.x = fmaf(dv, acc.z, bb.z);
    o1.y = fmaf(dv, acc.w, bb.w);
    half2 p0 = __float22half2_rn(o0);
    half2 p1 = __float22half2_rn(o1);
    uint2 w;
    w.x = *(const u32*)&p0;
    w.y = *(const u32*)&p1;
    ((uint2*)g_Bh)[(size_t)node * 32 + lane] = w;
}

// ---------------- tensor-core GEMM layout constants (128-row CTA tiles) ----------------
#define TILE_ROWS 128
#define A_PITCH 136              // halves (272 B rows)
#define W_PITCH 136
#define SC_PITCH 132             // floats
#define WH_BYTES (HID * W_PITCH * 2)            // 34816 (one W plane)
#define AT_BYTES (TILE_ROWS * A_PITCH * 2)      // 34816
#define L2_SMEM (2 * WH_BYTES + AT_BYTES + (5 * HID + HID) * 4)  // 107008 B
#define L3_SMEM (2 * WH_BYTES + AT_BYTES)                        // 104448 B

// split a float into hi/lo halves: w = hi + lo with |lo| <~ w*2^-12
__device__ __forceinline__ void split_h(float v, __half& hi, __half& lo) {
    hi = __float2half_rn(v);
    lo = __float2half_rn(v - __half2float(hi));
}

__device__ __forceinline__ void load_split_W(__half* Wh, __half* Wl,
                                             const float* __restrict__ W, int tid) {
    const float4* W4 = (const float4*)W;
    #pragma unroll
    for (int i = 0; i < 16; i++) {
        int idx4 = tid + 256 * i;                     // 0..4095
        int k = idx4 >> 5, c0 = (idx4 & 31) * 4;
        float4 v = W4[idx4];
        __half h0, l0, h1, l1, h2, l2, h3, l3;
        split_h(v.x, h0, l0); split_h(v.y, h1, l1);
        split_h(v.z, h2, l2); split_h(v.w, h3, l3);
        __half* wp = Wh + k * W_PITCH + c0;
        wp[0] = h0; wp[1] = h1; wp[2] = h2; wp[3] = h3;
        __half* lp = Wl + k * W_PITCH + c0;
        lp[0] = l0; lp[1] = l1; lp[2] = l2; lp[3] = l3;
    }
}

// shared mainloop + epilogue; epilogue scales output row by dinv[row] before fp16 store.
// Warp tile 32 rows x 64 cols: warp w -> rows [(w&3)*32, +32), cols [(w>>2)*64, +64).
__device__ __forceinline__ void mma_tile_and_store(const __half* Wh, const __half* Wl,
                                                   const __half* At, float* sc,
                                                   __half* gout, int row0, int tid) {
    int warp = tid >> 5;
    int rt = warp & 3;        // row subtile (32 rows)
    int ct = warp >> 2;       // col half (64 cols)
    wmma::fragment<wmma::accumulator, 16, 16, 16, float> fc[2][4];
    #pragma unroll
    for (int a = 0; a < 2; a++)
        #pragma unroll
        for (int j = 0; j < 4; j++) wmma::fill_fragment(fc[a][j], 0.0f);
    #pragma unroll
    for (int k0 = 0; k0 < 8; k0++) {
        wmma::fragment<wmma::matrix_a, 16, 16, 16, __half, wmma::row_major> fa0, fa1;
        wmma::load_matrix_sync(fa0, At + (rt * 32 + 0)  * A_PITCH + k0 * 16, A_PITCH);
        wmma::load_matrix_sync(fa1, At + (rt * 32 + 16) * A_PITCH + k0 * 16, A_PITCH);
        #pragma unroll
        for (int j = 0; j < 4; j++) {
            wmma::fragment<wmma::matrix_b, 16, 16, 16, __half, wmma::row_major> fb;
            wmma::load_matrix_sync(fb, Wh + k0 * 16 * W_PITCH + ct * 64 + j * 16, W_PITCH);
            wmma::mma_sync(fc[0][j], fa0, fb, fc[0][j]);
            wmma::mma_sync(fc[1][j], fa1, fb, fc[1][j]);
            wmma::load_matrix_sync(fb, Wl + k0 * 16 * W_PITCH + ct * 64 + j * 16, W_PITCH);
            wmma::mma_sync(fc[0][j], fa0, fb, fc[0][j]);
            wmma::mma_sync(fc[1][j], fa1, fb, fc[1][j]);
        }
    }
    __syncthreads();          // done reading W planes; reuse Wh+Wl as fp32 scratch
    #pragma unroll
    for (int a = 0; a < 2; a++)
        #pragma unroll
        for (int j = 0; j < 4; j++)
            wmma::store_matrix_sync(sc + (rt * 32 + a * 16) * SC_PITCH + ct * 64 + j * 16,
                                    fc[a][j], SC_PITCH, wmma::mem_row_major);
    __syncthreads();
    // convert scratch -> gout (fp16, scaled by dinv[row]): 128 rows x 32 col-quads
    #pragma unroll
    for (int i = 0; i < 16; i++) {
        int li = tid + 256 * i;               // 0..4095
        int r = li >> 5, c4 = (li & 31) * 4;
        int grow = row0 + r;
        if (grow < N_NODES) {
            float dvr = g_dinv[grow];
            float4 v = *(float4*)&sc[r * SC_PITCH + c4];
            half2 p0 = __floats2half2_rn(dvr * v.x, dvr * v.y);
            half2 p1 = __floats2half2_rn(dvr * v.z, dvr * v.w);
            uint2 w;
            w.x = *(const u32*)&p0;
            w.y = *(const u32*)&p1;
            *(uint2*)&gout[(size_t)grow * HID + c4] = w;
        }
    }
}

// ---------------- layer-2 GEMM (fused layer-1 linear): Ah = dinv * (relu(XA@W1+b1) @ W2) ----------------
__global__ __launch_bounds__(256) void k_gemm_l2(const float* __restrict__ W1,
                                                 const float* __restrict__ b1,
                                                 const float* __restrict__ W2) {
    extern __shared__ char shc[];
    __half* Wh  = (__half*)shc;                       // [128][136] W2 hi
    __half* Wl  = Wh + HID * W_PITCH;                 // [128][136] W2 lo
    __half* At  = Wl + HID * W_PITCH;                 // [128][136] input tile
    float*  W1s = (float*)(At + TILE_ROWS * A_PITCH); // [5][128]
    float*  b1s = W1s + 5 * HID;                      // [128]
    int tid = threadIdx.x;

    load_split_W(Wh, Wl, W2, tid);
    for (int i = tid; i < 5 * HID; i += 256) W1s[i] = W1[i];
    if (tid < HID) b1s[tid] = b1[tid];
    __syncthreads();

    int warp = tid >> 5, lane = tid & 31;
    int row0 = blockIdx.x * TILE_ROWS;

    // prologue: relu(XA@W1 + b1) -> At (fp32 math, fp16 store); warp handles 16 rows
    {
        float4 w1v[5];
        #pragma unroll
        for (int k = 0; k < 5; k++) w1v[k] = ((const float4*)(W1s + k * HID))[lane];
        float4 b1v = ((const float4*)b1s)[lane];
        #pragma unroll
        for (int rr = 0; rr < 16; rr++) {
            int node = row0 + warp * 16 + rr;
            float4 h = make_float4(0.f, 0.f, 0.f, 0.f);
            if (node < N_NODES) {
                const float* xa = g_XA + (size_t)node * 5;
                float xk[5];
                #pragma unroll
                for (int k = 0; k < 5; k++) xk[k] = xa[k];
                h = b1v;
                #pragma unroll
                for (int k = 0; k < 5; k++) {
                    h.x = fmaf(xk[k], w1v[k].x, h.x);
                    h.y = fmaf(xk[k], w1v[k].y, h.y);
                    h.z = fmaf(xk[k], w1v[k].z, h.z);
                    h.w = fmaf(xk[k], w1v[k].w, h.w);
                }
                h.x = fmaxf(h.x, 0.f); h.y = fmaxf(h.y, 0.f);
                h.z = fmaxf(h.z, 0.f); h.w = fmaxf(h.w, 0.f);
            }
            __half* dp = At + (warp * 16 + rr) * A_PITCH + lane * 4;
            *(half2*)dp       = __floats2half2_rn(h.x, h.y);
            *(half2*)(dp + 2) = __floats2half2_rn(h.z, h.w);
        }
    }
    __syncthreads();

    mma_tile_and_store(Wh, Wl, At, (float*)Wh, g_Ah, row0, tid);
}

// ---------------- layer-3 GEMM: Ah = dinv * (relu(Bh) @ W3) ----------------
__global__ __launch_bounds__(256) void k_gemm_l3(const float* __restrict__ W3) {
    extern __shared__ char shc[];
    __half* Wh = (__half*)shc;                        // [128][136] hi
    __half* Wl = Wh + HID * W_PITCH;                  // [128][136] lo
    __half* At = Wl + HID * W_PITCH;                  // [128][136]
    int tid = threadIdx.x;

    load_split_W(Wh, Wl, W3, tid);

    int row0 = blockIdx.x * TILE_ROWS;
    // tile load: relu(Bh) -> At: 128 rows x 16 uint4 (8 halves each)
    half2 z2 = __floats2half2_rn(0.f, 0.f);
    #pragma unroll
    for (int i = 0; i < 8; i++) {
        int li = tid + 256 * i;               // 0..2047: r = li>>4, q = li&15
        int r = li >> 4, q = li & 15;
        int grow = row0 + r;
        uint4 v = make_uint4(0u, 0u, 0u, 0u);
        if (grow < N_NODES) v = *(const uint4*)&g_Bh[(size_t)grow * HID + q * 8];
        half2 h0 = __hmax2(*(half2*)&v.x, z2);
        half2 h1 = __hmax2(*(half2*)&v.y, z2);
        half2 h2 = __hmax2(*(half2*)&v.z, z2);
        half2 h3 = __hmax2(*(half2*)&v.w, z2);
        __half* dp = At + r * A_PITCH + q * 8;
        *(half2*)(dp + 0) = h0;
        *(half2*)(dp + 2) = h1;
        *(half2*)(dp + 4) = h2;
        *(half2*)(dp + 6) = h3;
    }
    __syncthreads();

    mma_tile_and_store(Wh, Wl, At, (float*)Wh, g_Ah, row0, tid);
}

// ---------------- layer-3 aggregation fused with final FC ----------------
__global__ __launch_bounds__(256) void k_agg_final(const float* __restrict__ bias,
                                                   const float* __restrict__ Wfc,
                                                   const float* __restrict__ bfc,
                                                   float* __restrict__ out) {
    int g = blockIdx.x * blockDim.x + threadIdx.x;
    int node = g >> 5;
    int lane = g & 31;
    if (node >= N_NODES) return;

    const uint2* __restrict__ A2 = (const uint2*)g_Ah;
    float dv = g_dinv[node];
    uint2 raw = A2[(size_t)node * 32 + lane];
    float2 s0 = __half22float2(*(const half2*)&raw.x);
    float2 s1 = __half22float2(*(const half2*)&raw.y);
    float4 acc;
    acc.x = s0.x; acc.y = s0.y; acc.z = s1.x; acc.w = s1.y;

    int cnt = g_cnt[node];
    int start = g_off[node] - cnt;
    for (int j0 = 0; j0 < cnt; j0 += 32) {
        int  rem = cnt - j0;
        bool ok  = lane < rem;
        int  sv  = ok ? g_esrc[start + j0 + lane] : 0;
        int m = min(32, rem);
        #pragma unroll 8
        for (int j = 0; j < m; j++) {
            int sj = __shfl_sync(0xffffffffu, sv, j);
            uint2 r = A2[(size_t)sj * 32 + lane];
            float2 f0 = __half22float2(*(const half2*)&r.x);
            float2 f1 = __half22float2(*(const half2*)&r.y);
            acc.x += f0.x; acc.y += f0.y;
            acc.z += f1.x; acc.w += f1.y;
        }
    }
    float4 bb = ((const float4*)bias)[lane];
    float4 w  = ((const float4*)Wfc)[lane];
    float dot = fmaxf(fmaf(dv, acc.x, bb.x), 0.f) * w.x
              + fmaxf(fmaf(dv, acc.y, bb.y), 0.f) * w.y
              + fmaxf(fmaf(dv, acc.z, bb.z), 0.f) * w.z
              + fmaxf(fmaf(dv, acc.w, bb.w), 0.f) * w.w;
    #pragma unroll
    for (int o = 16; o > 0; o >>= 1) dot += __shfl_xor_sync(0xffffffffu, dot, o);
    if (lane == 0) out[node] = dot + bfc[0];
}

// ---------------- launcher ----------------
extern "C" void kernel_launch(void* const* d_in, const int* in_sizes, int n_in,
                              void* d_out, int out_size) {
    const float* x   = (const float*)d_in[0];
    const int*   ei  = (const int*)  d_in[1];
    const float* W1  = (const float*)d_in[2];
    const float* b1  = (const float*)d_in[3];
    const float* W2  = (const float*)d_in[4];
    const float* b2  = (const float*)d_in[5];
    const float* W3  = (const float*)d_in[6];
    const float* b3  = (const float*)d_in[7];
    const float* Wfc = (const float*)d_in[8];
    const float* bfc = (const float*)d_in[9];
    float* out = (float*)d_out;

    const int* src = ei;
    const int* dst = ei + N_EDGES;

    cudaFuncSetAttribute(k_gemm_l2, cudaFuncAttributeMaxDynamicSharedMemorySize, L2_SMEM);
    cudaFuncSetAttribute(k_gemm_l3, cudaFuncAttributeMaxDynamicSharedMemorySize, L3_SMEM);

    const int T = 256;
    int nb_nodes = (N_NODES + T - 1) / T;
    int nb_half  = (N_EDGES / 2 + T - 1) / T;
    int nb_warps = (N_NODES * 32 + T - 1) / T;
    int nb_gemm  = (N_NODES + TILE_ROWS - 1) / TILE_ROWS;

    // CSR build (g_cnt zeroed via async memset — graph-capturable, no alloc)
    void* cntPtr = nullptr;
    cudaGetSymbolAddress(&cntPtr, g_cnt);
    cudaMemsetAsync(cntPtr, 0, N_NODES * sizeof(int));
    k_deg_count<<<nb_half, T>>>(dst);
    k_bsum     <<<NB_SCAN, SCAN_B>>>(x);
    k_boff     <<<NB_SCAN, SCAN_B>>>();
    k_fill     <<<nb_half, T>>>(src, dst);

    // pipeline
    k_agg_x   <<<nb_nodes, T>>>();
    k_gemm_l2 <<<nb_gemm, T, L2_SMEM>>>(W1, b1, W2);   // Ah = dinv*(relu(XA@W1+b1) @ W2)
    k_agg     <<<nb_warps, T>>>(b2);                    // Bh = dinv*(sum Ah) + b2
    k_gemm_l3 <<<nb_gemm, T, L3_SMEM>>>(W3);            // Ah = dinv*(relu(Bh) @ W3)
    k_agg_final<<<nb_warps, T>>>(b3, Wfc, bfc, out);    // out = relu(dinv*sum+b3)·Wfc + bfc
}